// round 1
// baseline (speedup 1.0000x reference)
#include <cuda_runtime.h>
#include <cstdint>
#include <cstddef>

// Problem constants (match reference_code)
#define N_NODES 100000
#define N_EDGES 1600000
#define F_IN    128
#define F_HID   128
#define F_OUT   64

// ---------------------------------------------------------------------------
// Scratch (device globals: allocation-free per harness rules)
// ---------------------------------------------------------------------------
__device__ float g_deg [N_NODES];
__device__ float g_dinv[N_NODES];
__device__ float g_h1  [(size_t)N_NODES * F_HID];  // g1 = dinv * (x @ W1)   (gather source, layer 1)
__device__ float g_a1  [(size_t)N_NODES * F_HID];  // aggregation buffer, init = g1 (self loop)
__device__ float g_h2  [(size_t)N_NODES * F_OUT];  // g2 = dinv * (y1 @ W2)  (gather source, layer 2)

// ---------------------------------------------------------------------------
// Degree / normalization
// ---------------------------------------------------------------------------
__global__ void init_deg_kernel(int n) {
    int i = blockIdx.x * blockDim.x + threadIdx.x;
    if (i < n) g_deg[i] = 1.0f;  // self-loop contributes 1 to in-degree
}

__global__ void accum_deg_kernel(const int* __restrict__ dst, int E) {
    int e = blockIdx.x * blockDim.x + threadIdx.x;
    if (e < E) atomicAdd(&g_deg[dst[e]], 1.0f);
}

__global__ void dinv_kernel(int n) {
    int i = blockIdx.x * blockDim.x + threadIdx.x;
    if (i < n) g_dinv[i] = rsqrtf(g_deg[i]);
}

// ---------------------------------------------------------------------------
// Fused GEMM + dinv row-scale epilogue.
//   out1[r,:] = out2[r,:] = dinv[r] * (X[r,:] @ W)      (K = 128 fixed)
// Block tile: 128 rows x NOUT cols, whole K in one pass.
// 256 threads; micro-tile TM x 8 per thread.
// ---------------------------------------------------------------------------
#define XPITCH 132   // 128 + 4 floats: breaks bank aliasing on xs reads

template <int NOUT>
__global__ void gemm_scale_kernel(const float* __restrict__ X,
                                  const float* __restrict__ W,
                                  float* __restrict__ out1,
                                  float* __restrict__ out2,
                                  int nrows)
{
    constexpr int TXN = NOUT / 8;      // threads across columns (16 or 8)
    constexpr int TYN = 256 / TXN;     // threads across rows    (16 or 32)
    constexpr int TM  = 128 / TYN;     // rows per thread        (8 or 4)

    extern __shared__ float sm[];
    float* xs = sm;                    // [128][XPITCH]
    float* ws = sm + 128 * XPITCH;     // [128][NOUT]

    const int row0 = blockIdx.x * 128;
    const int tid  = threadIdx.x;

    // Load W (128 x NOUT) fully into smem, float4, coalesced
    {
        const float4* Wv = (const float4*)W;
        float4* wsv = (float4*)ws;
        for (int i = tid; i < 128 * NOUT / 4; i += 256) wsv[i] = Wv[i];
    }
    // Load X tile (128 rows x 128 floats) into smem with pitch; zero-fill tail rows
    {
        for (int i = tid; i < 128 * 32; i += 256) {
            int r = i >> 5;           // row within tile
            int q = i & 31;           // float4 column group
            float4 v = make_float4(0.f, 0.f, 0.f, 0.f);
            int gr = row0 + r;
            if (gr < nrows) v = ((const float4*)X)[(size_t)gr * 32 + q];
            *(float4*)(xs + r * XPITCH + q * 4) = v;   // 16B-aligned (XPITCH*4 % 16 == 0)
        }
    }
    __syncthreads();

    const int tx = tid % TXN;
    const int ty = tid / TXN;

    float acc[TM][8];
#pragma unroll
    for (int i = 0; i < TM; i++)
#pragma unroll
        for (int j = 0; j < 8; j++) acc[i][j] = 0.f;

#pragma unroll 4
    for (int k = 0; k < 128; k++) {
        const float4 w0 = *(const float4*)(ws + k * NOUT + tx * 8);
        const float4 w1 = *(const float4*)(ws + k * NOUT + tx * 8 + 4);
#pragma unroll
        for (int i = 0; i < TM; i++) {
            const float xv = xs[(ty + i * TYN) * XPITCH + k];  // interleaved row map
            acc[i][0] += xv * w0.x; acc[i][1] += xv * w0.y;
            acc[i][2] += xv * w0.z; acc[i][3] += xv * w0.w;
            acc[i][4] += xv * w1.x; acc[i][5] += xv * w1.y;
            acc[i][6] += xv * w1.z; acc[i][7] += xv * w1.w;
        }
    }

    // Epilogue: scale by dinv[row], write to both outputs
#pragma unroll
    for (int i = 0; i < TM; i++) {
        const int r = row0 + ty + i * TYN;
        if (r < nrows) {
            const float dv = g_dinv[r];
            float4 o0, o1;
            o0.x = acc[i][0] * dv; o0.y = acc[i][1] * dv;
            o0.z = acc[i][2] * dv; o0.w = acc[i][3] * dv;
            o1.x = acc[i][4] * dv; o1.y = acc[i][5] * dv;
            o1.z = acc[i][6] * dv; o1.w = acc[i][7] * dv;
            const size_t base = (size_t)r * NOUT + tx * 8;
            *(float4*)(out1 + base)     = o0;
            *(float4*)(out1 + base + 4) = o1;
            *(float4*)(out2 + base)     = o0;
            *(float4*)(out2 + base + 4) = o1;
        }
    }
}

// ---------------------------------------------------------------------------
// Edge scatter: a[dst,:] += g[src,:]  via vectorized global reductions.
// FEAT4 = feature-width / 4 (float4 units per row). One thread per (edge, float4).
// ---------------------------------------------------------------------------
template <int FEAT4>  // 32 for 128 feats, 16 for 64 feats
__global__ void scatter_kernel(const int* __restrict__ src,
                               const int* __restrict__ dst,
                               const float4* __restrict__ g,
                               float4* __restrict__ a,
                               int E)
{
    const long long idx = (long long)blockIdx.x * blockDim.x + threadIdx.x;
    if (idx >= (long long)E * FEAT4) return;
    const int e = (int)(idx / FEAT4);
    const int q = (int)(idx % FEAT4);
    const int s = __ldg(src + e);
    const int d = __ldg(dst + e);
    const float4 v = g[(size_t)s * FEAT4 + q];
    float4* p = a + (size_t)d * FEAT4 + q;
    asm volatile("red.global.add.v4.f32 [%0], {%1,%2,%3,%4};"
                 :: "l"(p), "f"(v.x), "f"(v.y), "f"(v.z), "f"(v.w)
                 : "memory");
}

// ---------------------------------------------------------------------------
// y1 = relu(dinv * a1 + b1), in place on a1
// ---------------------------------------------------------------------------
__global__ void relu_mid_kernel(const float* __restrict__ b1, int n) {
    const long long idx = (long long)blockIdx.x * blockDim.x + threadIdx.x;
    if (idx >= (long long)n * F_HID) return;
    const int i = (int)(idx >> 7);
    const int c = (int)(idx & 127);
    float v = g_a1[idx] * g_dinv[i] + b1[c];
    g_a1[idx] = v > 0.f ? v : 0.f;
}

// ---------------------------------------------------------------------------
// out = dinv * out + b2, in place on d_out
// ---------------------------------------------------------------------------
__global__ void finalize_kernel(float* __restrict__ out, const float* __restrict__ b2, int n) {
    const long long idx = (long long)blockIdx.x * blockDim.x + threadIdx.x;
    if (idx >= (long long)n * F_OUT) return;
    const int i = (int)(idx >> 6);
    const int c = (int)(idx & 63);
    out[idx] = out[idx] * g_dinv[i] + b2[c];
}

// ---------------------------------------------------------------------------
// Launch
// ---------------------------------------------------------------------------
extern "C" void kernel_launch(void* const* d_in, const int* in_sizes, int n_in,
                              void* d_out, int out_size)
{
    const float* x   = (const float*)d_in[0];   // [N, 128]
    const int*   ei  = (const int*)  d_in[1];   // [2, E] row-major: src then dst
    const float* W1  = (const float*)d_in[2];   // [128, 128]
    const float* b1  = (const float*)d_in[3];   // [128]
    const float* W2  = (const float*)d_in[4];   // [128, 64]
    const float* b2  = (const float*)d_in[5];   // [64]
    float* out = (float*)d_out;                  // [N, 64]

    const int N = in_sizes[0] / F_IN;
    const int E = in_sizes[1] / 2;
    const int* src = ei;
    const int* dst = ei + E;

    // Resolve device-global scratch addresses
    float *p_h1, *p_a1, *p_h2;
    cudaGetSymbolAddress((void**)&p_h1, g_h1);
    cudaGetSymbolAddress((void**)&p_a1, g_a1);
    cudaGetSymbolAddress((void**)&p_h2, g_h2);

    // Dynamic smem sizes for the GEMMs (> 48KB, need opt-in)
    const int smem1 = (128 * XPITCH + 128 * F_HID) * (int)sizeof(float);  // 133,120 B
    const int smem2 = (128 * XPITCH + 128 * F_OUT) * (int)sizeof(float);  // 100,352 B
    cudaFuncSetAttribute(gemm_scale_kernel<F_HID>,
                         cudaFuncAttributeMaxDynamicSharedMemorySize, smem1);
    cudaFuncSetAttribute(gemm_scale_kernel<F_OUT>,
                         cudaFuncAttributeMaxDynamicSharedMemorySize, smem2);

    const int T = 256;
    // 1. degree (incl. self-loop) and dinv
    init_deg_kernel<<<(N + T - 1) / T, T>>>(N);
    accum_deg_kernel<<<(E + T - 1) / T, T>>>(dst, E);
    dinv_kernel<<<(N + T - 1) / T, T>>>(N);

    // 2. layer 1: g1 = dinv*(x@W1) -> h1 and a1 (a1 init = self-loop term)
    const int gblk = (N + 127) / 128;
    gemm_scale_kernel<F_HID><<<gblk, T, smem1>>>(x, W1, p_h1, p_a1, N);

    // 3. scatter edges: a1[dst] += h1[src]
    {
        long long total = (long long)E * 32;
        int blocks = (int)((total + T - 1) / T);
        scatter_kernel<32><<<blocks, T>>>(src, dst, (const float4*)p_h1, (float4*)p_a1, E);
    }

    // 4. y1 = relu(dinv*a1 + b1), in place
    {
        long long total = (long long)N * F_HID;
        relu_mid_kernel<<<(int)((total + T - 1) / T), T>>>(b1, N);
    }

    // 5. layer 2 GEMM: g2 = dinv*(y1@W2) -> h2 and d_out (d_out init = self-loop term)
    gemm_scale_kernel<F_OUT><<<gblk, T, smem2>>>(p_a1, W2, p_h2, out, N);

    // 6. scatter edges: out[dst] += h2[src]
    {
        long long total = (long long)E * 16;
        int blocks = (int)((total + T - 1) / T);
        scatter_kernel<16><<<blocks, T>>>(src, dst, (const float4*)p_h2, (float4*)out, E);
    }

    // 7. out = dinv*out + b2
    {
        long long total = (long long)N * F_OUT;
        finalize_kernel<<<(int)((total + T - 1) / T), T>>>(out, b2, N);
    }
}

// round 2
// speedup vs baseline: 1.1418x; 1.1418x over previous
#include <cuda_runtime.h>
#include <cstdint>
#include <cstddef>

// Problem constants (match reference_code)
#define N_NODES 100000
#define N_EDGES 1600000
#define F_IN    128
#define F_HID   128
#define F_OUT   64

typedef unsigned long long ull;

// ---------------------------------------------------------------------------
// Scratch (device globals: allocation-free per harness rules)
// ---------------------------------------------------------------------------
__device__ float g_deg [N_NODES];
__device__ float g_dinv[N_NODES];
__device__ float g_h1  [(size_t)N_NODES * F_HID];  // g1 = dinv * (x @ W1)
__device__ float g_a1  [(size_t)N_NODES * F_HID];  // agg buffer, init = g1 (self loop)
__device__ float g_h2  [(size_t)N_NODES * F_OUT];  // g2 = dinv * (y1 @ W2)

// ---------------------------------------------------------------------------
// Packed fp32x2 helpers (sm_100+)
// ---------------------------------------------------------------------------
__device__ __forceinline__ void ffma2(ull& d, ull a, ull b) {
    asm("fma.rn.f32x2 %0, %1, %2, %0;" : "+l"(d) : "l"(a), "l"(b));
}
__device__ __forceinline__ ull pack2(float x) {
    ull r;
    asm("mov.b64 %0, {%1, %1};" : "=l"(r) : "f"(x));
    return r;
}
__device__ __forceinline__ float2 unpack2(ull v) {
    float2 r;
    asm("mov.b64 {%0, %1}, %2;" : "=f"(r.x), "=f"(r.y) : "l"(v));
    return r;
}

// ---------------------------------------------------------------------------
// Degree / normalization
// ---------------------------------------------------------------------------
__global__ void init_deg_kernel(int n) {
    int i = blockIdx.x * blockDim.x + threadIdx.x;
    if (i < n) g_deg[i] = 1.0f;  // self-loop contributes 1 to in-degree
}

__global__ void accum_deg_kernel(const int* __restrict__ dst, int E) {
    int e = blockIdx.x * blockDim.x + threadIdx.x;
    if (e < E) atomicAdd(&g_deg[dst[e]], 1.0f);
}

__global__ void dinv_kernel(int n) {
    int i = blockIdx.x * blockDim.x + threadIdx.x;
    if (i < n) g_dinv[i] = rsqrtf(g_deg[i]);
}

// ---------------------------------------------------------------------------
// Fused GEMM + dinv row-scale epilogue, packed fp32x2 math.
//   out1[r,:] = out2[r,:] = dinv[r] * (X[r,:] @ W)      (K = 128 fixed)
// Block tile: 128 rows x NOUT cols. W fully resident in smem; X staged in
// K-chunks of 64 to keep smem <= ~100KB (2 blocks/SM).
// 256 threads; micro-tile TM rows x 8 cols (4 packed f32x2 accumulators/row).
// ---------------------------------------------------------------------------
#define KCHUNK 64
#define XP     68    // KCHUNK + 4 pitch

template <int NOUT>
__global__ __launch_bounds__(256, 2)
void gemm_scale_kernel(const float* __restrict__ X,
                       const float* __restrict__ W,
                       float* __restrict__ out1,
                       float* __restrict__ out2,
                       int nrows)
{
    constexpr int TXN = NOUT / 8;      // threads across columns (16 or 8)
    constexpr int TYN = 256 / TXN;     // threads across rows    (16 or 32)
    constexpr int TM  = 128 / TYN;     // rows per thread        (8 or 4)

    extern __shared__ float sm[];
    float* ws = sm;                    // [128][NOUT], resident
    float* xs = sm + 128 * NOUT;       // [128][XP], K-chunk staging

    const int row0 = blockIdx.x * 128;
    const int tid  = threadIdx.x;
    const int tx   = tid % TXN;
    const int ty   = tid / TXN;

    // Load W (128 x NOUT) fully into smem, float4, coalesced
    {
        const float4* Wv = (const float4*)W;
        float4* wsv = (float4*)ws;
        for (int i = tid; i < 128 * NOUT / 4; i += 256) wsv[i] = Wv[i];
    }

    ull acc[TM][4];
#pragma unroll
    for (int i = 0; i < TM; i++)
#pragma unroll
        for (int j = 0; j < 4; j++) acc[i][j] = 0ull;

    for (int kc = 0; kc < 128; kc += KCHUNK) {
        __syncthreads();   // guard xs reuse (and W load on first pass ordering below)
        // Stage X chunk: 128 rows x KCHUNK floats (float4, coalesced, zero-fill tail)
        for (int i = tid; i < 128 * (KCHUNK / 4); i += 256) {
            int r = i >> 4;            // / (KCHUNK/4) = /16
            int q = i & 15;            // % 16
            float4 v = make_float4(0.f, 0.f, 0.f, 0.f);
            int gr = row0 + r;
            if (gr < nrows) v = ((const float4*)X)[(size_t)gr * 32 + (kc >> 2) + q];
            *(float4*)(xs + r * XP + q * 4) = v;   // 16B aligned: XP*4 % 16 == 16? 272%16=0 ✓
        }
        __syncthreads();

#pragma unroll 8
        for (int k = 0; k < KCHUNK; k++) {
            const ulonglong2 wv0 = *(const ulonglong2*)(ws + (size_t)(kc + k) * NOUT + tx * 8);
            const ulonglong2 wv1 = *(const ulonglong2*)(ws + (size_t)(kc + k) * NOUT + tx * 8 + 4);
#pragma unroll
            for (int i = 0; i < TM; i++) {
                const ull xx = pack2(xs[(ty + i * TYN) * XP + k]);
                ffma2(acc[i][0], xx, wv0.x);
                ffma2(acc[i][1], xx, wv0.y);
                ffma2(acc[i][2], xx, wv1.x);
                ffma2(acc[i][3], xx, wv1.y);
            }
        }
    }

    // Epilogue: scale by dinv[row], write to both outputs
#pragma unroll
    for (int i = 0; i < TM; i++) {
        const int r = row0 + ty + i * TYN;
        if (r < nrows) {
            const float dv = g_dinv[r];
            const float2 p0 = unpack2(acc[i][0]);
            const float2 p1 = unpack2(acc[i][1]);
            const float2 p2 = unpack2(acc[i][2]);
            const float2 p3 = unpack2(acc[i][3]);
            float4 o0, o1;
            o0.x = p0.x * dv; o0.y = p0.y * dv;
            o0.z = p1.x * dv; o0.w = p1.y * dv;
            o1.x = p2.x * dv; o1.y = p2.y * dv;
            o1.z = p3.x * dv; o1.w = p3.y * dv;
            const size_t base = (size_t)r * NOUT + tx * 8;
            *(float4*)(out1 + base)     = o0;
            *(float4*)(out1 + base + 4) = o1;
            *(float4*)(out2 + base)     = o0;
            *(float4*)(out2 + base + 4) = o1;
        }
    }
}

// ---------------------------------------------------------------------------
// Edge scatter: a[dst,:] += g[src,:]  via vectorized global reductions.
// ---------------------------------------------------------------------------
template <int FEAT4>  // 32 for 128 feats, 16 for 64 feats
__global__ void scatter_kernel(const int* __restrict__ src,
                               const int* __restrict__ dst,
                               const float4* __restrict__ g,
                               float4* __restrict__ a,
                               int E)
{
    const long long idx = (long long)blockIdx.x * blockDim.x + threadIdx.x;
    if (idx >= (long long)E * FEAT4) return;
    const int e = (int)(idx / FEAT4);
    const int q = (int)(idx % FEAT4);
    const int s = __ldg(src + e);
    const int d = __ldg(dst + e);
    const float4 v = g[(size_t)s * FEAT4 + q];
    float4* p = a + (size_t)d * FEAT4 + q;
    asm volatile("red.global.add.v4.f32 [%0], {%1,%2,%3,%4};"
                 :: "l"(p), "f"(v.x), "f"(v.y), "f"(v.z), "f"(v.w)
                 : "memory");
}

// ---------------------------------------------------------------------------
// y1 = relu(dinv * a1 + b1), in place on a1
// ---------------------------------------------------------------------------
__global__ void relu_mid_kernel(const float* __restrict__ b1, int n) {
    const long long idx = (long long)blockIdx.x * blockDim.x + threadIdx.x;
    if (idx >= (long long)n * F_HID) return;
    const int i = (int)(idx >> 7);
    const int c = (int)(idx & 127);
    float v = g_a1[idx] * g_dinv[i] + b1[c];
    g_a1[idx] = v > 0.f ? v : 0.f;
}

// ---------------------------------------------------------------------------
// out = dinv * out + b2, in place on d_out
// ---------------------------------------------------------------------------
__global__ void finalize_kernel(float* __restrict__ out, const float* __restrict__ b2, int n) {
    const long long idx = (long long)blockIdx.x * blockDim.x + threadIdx.x;
    if (idx >= (long long)n * F_OUT) return;
    const int i = (int)(idx >> 6);
    const int c = (int)(idx & 63);
    out[idx] = out[idx] * g_dinv[i] + b2[c];
}

// ---------------------------------------------------------------------------
// Launch
// ---------------------------------------------------------------------------
extern "C" void kernel_launch(void* const* d_in, const int* in_sizes, int n_in,
                              void* d_out, int out_size)
{
    const float* x   = (const float*)d_in[0];   // [N, 128]
    const int*   ei  = (const int*)  d_in[1];   // [2, E]: src row then dst row
    const float* W1  = (const float*)d_in[2];   // [128, 128]
    const float* b1  = (const float*)d_in[3];   // [128]
    const float* W2  = (const float*)d_in[4];   // [128, 64]
    const float* b2  = (const float*)d_in[5];   // [64]
    float* out = (float*)d_out;                  // [N, 64]

    const int N = in_sizes[0] / F_IN;
    const int E = in_sizes[1] / 2;
    const int* src = ei;
    const int* dst = ei + E;

    float *p_h1, *p_a1, *p_h2;
    cudaGetSymbolAddress((void**)&p_h1, g_h1);
    cudaGetSymbolAddress((void**)&p_a1, g_a1);
    cudaGetSymbolAddress((void**)&p_h2, g_h2);

    // Dynamic smem: W resident + X K-chunk buffer
    const int smem1 = (128 * F_HID + 128 * XP) * (int)sizeof(float);  // 65536+34816 = 100352
    const int smem2 = (128 * F_OUT + 128 * XP) * (int)sizeof(float);  // 32768+34816 = 67584
    cudaFuncSetAttribute(gemm_scale_kernel<F_HID>,
                         cudaFuncAttributeMaxDynamicSharedMemorySize, smem1);
    cudaFuncSetAttribute(gemm_scale_kernel<F_OUT>,
                         cudaFuncAttributeMaxDynamicSharedMemorySize, smem2);

    const int T = 256;
    // 1. degree (incl. self-loop) and dinv
    init_deg_kernel<<<(N + T - 1) / T, T>>>(N);
    accum_deg_kernel<<<(E + T - 1) / T, T>>>(dst, E);
    dinv_kernel<<<(N + T - 1) / T, T>>>(N);

    // 2. layer 1: g1 = dinv*(x@W1) -> h1 and a1 (a1 init = self-loop term)
    const int gblk = (N + 127) / 128;
    gemm_scale_kernel<F_HID><<<gblk, T, smem1>>>(x, W1, p_h1, p_a1, N);

    // 3. scatter edges: a1[dst] += h1[src]
    {
        long long total = (long long)E * 32;
        int blocks = (int)((total + T - 1) / T);
        scatter_kernel<32><<<blocks, T>>>(src, dst, (const float4*)p_h1, (float4*)p_a1, E);
    }

    // 4. y1 = relu(dinv*a1 + b1), in place
    {
        long long total = (long long)N * F_HID;
        relu_mid_kernel<<<(int)((total + T - 1) / T), T>>>(b1, N);
    }

    // 5. layer 2: g2 = dinv*(y1@W2) -> h2 and d_out (d_out init = self-loop term)
    gemm_scale_kernel<F_OUT><<<gblk, T, smem2>>>(p_a1, W2, p_h2, out, N);

    // 6. scatter edges: out[dst] += h2[src]
    {
        long long total = (long long)E * 16;
        int blocks = (int)((total + T - 1) / T);
        scatter_kernel<16><<<blocks, T>>>(src, dst, (const float4*)p_h2, (float4*)out, E);
    }

    // 7. out = dinv*out + b2
    {
        long long total = (long long)N * F_OUT;
        finalize_kernel<<<(int)((total + T - 1) / T), T>>>(out, b2, N);
    }
}

// round 4
// speedup vs baseline: 1.1538x; 1.0105x over previous
#include <cuda_runtime.h>
#include <cstdint>
#include <cstddef>

#define N_NODES 100000
#define N_EDGES 1600000
#define F_IN    128
#define F_HID   128
#define F_OUT   64

typedef unsigned long long ull;

// ---------------------------------------------------------------------------
// Scratch (device globals)
// ---------------------------------------------------------------------------
__device__ int   g_cnt     [N_NODES];
__device__ int   g_rowstart[N_NODES + 1];
__device__ int   g_cursor  [N_NODES];
__device__ int   g_csr     [N_EDGES];
__device__ float g_dinv    [N_NODES];
__device__ float g_h1 [(size_t)N_NODES * F_HID];  // dinv * (x @ W1)
__device__ float g_y1 [(size_t)N_NODES * F_HID];  // relu(dinv*agg + b1)
__device__ float g_h2 [(size_t)N_NODES * F_OUT];  // dinv * (y1 @ W2)

// ---------------------------------------------------------------------------
// Packed fp32x2 helpers (sm_100+)
// ---------------------------------------------------------------------------
__device__ __forceinline__ void ffma2(ull& d, ull a, ull b) {
    asm("fma.rn.f32x2 %0, %1, %2, %0;" : "+l"(d) : "l"(a), "l"(b));
}
__device__ __forceinline__ ull pack2(float x) {
    ull r; asm("mov.b64 %0, {%1, %1};" : "=l"(r) : "f"(x)); return r;
}
__device__ __forceinline__ float2 unpack2(ull v) {
    float2 r; asm("mov.b64 {%0, %1}, %2;" : "=f"(r.x), "=f"(r.y) : "l"(v)); return r;
}

// ---------------------------------------------------------------------------
// CSR build
// ---------------------------------------------------------------------------
__global__ void zero_cnt_kernel(int n) {
    int i = blockIdx.x * blockDim.x + threadIdx.x;
    if (i < n) g_cnt[i] = 0;
}

__global__ void hist_kernel(const int* __restrict__ dst, int E) {
    int e = blockIdx.x * blockDim.x + threadIdx.x;
    if (e < E) atomicAdd(&g_cnt[dst[e]], 1);
}

// Single-block scan over N counts -> rowstart (exclusive), cursor copy, dinv.
#define SCAN_T 1024
__global__ void scan_kernel(int N) {
    __shared__ int ssum[SCAN_T];
    const int t  = threadIdx.x;
    const int CH = (N + SCAN_T - 1) / SCAN_T;
    const int lo = t * CH;
    const int hi = min(lo + CH, N);
    int s = 0;
    for (int i = lo; i < hi; i++) s += g_cnt[i];
    ssum[t] = s;
    __syncthreads();
    for (int off = 1; off < SCAN_T; off <<= 1) {
        int v = (t >= off) ? ssum[t - off] : 0;
        __syncthreads();
        if (t >= off) ssum[t] += v;
        __syncthreads();
    }
    int run = (t > 0) ? ssum[t - 1] : 0;
    for (int i = lo; i < hi; i++) {
        int c = g_cnt[i];
        g_rowstart[i] = run;
        g_cursor[i]   = run;
        g_dinv[i]     = rsqrtf((float)c + 1.0f);  // +1 for self-loop
        run += c;
    }
    if (t == SCAN_T - 1) g_rowstart[N] = run;
}

__global__ void place_kernel(const int* __restrict__ src,
                             const int* __restrict__ dst, int E) {
    int e = blockIdx.x * blockDim.x + threadIdx.x;
    if (e < E) {
        int d = dst[e];
        int p = atomicAdd(&g_cursor[d], 1);
        g_csr[p] = src[e];
    }
}

// ---------------------------------------------------------------------------
// Fused GEMM + dinv row-scale epilogue, packed fp32x2 math (single output).
// ---------------------------------------------------------------------------
#define KCHUNK 64
#define XP     68

template <int NOUT>
__global__ __launch_bounds__(256, 2)
void gemm_scale_kernel(const float* __restrict__ X,
                       const float* __restrict__ W,
                       float* __restrict__ out,
                       int nrows)
{
    constexpr int TXN = NOUT / 8;
    constexpr int TYN = 256 / TXN;
    constexpr int TM  = 128 / TYN;

    extern __shared__ float sm[];
    float* ws = sm;
    float* xs = sm + 128 * NOUT;

    const int row0 = blockIdx.x * 128;
    const int tid  = threadIdx.x;
    const int tx   = tid % TXN;
    const int ty   = tid / TXN;

    {
        const float4* Wv = (const float4*)W;
        float4* wsv = (float4*)ws;
        for (int i = tid; i < 128 * NOUT / 4; i += 256) wsv[i] = Wv[i];
    }

    ull acc[TM][4];
#pragma unroll
    for (int i = 0; i < TM; i++)
#pragma unroll
        for (int j = 0; j < 4; j++) acc[i][j] = 0ull;

    for (int kc = 0; kc < 128; kc += KCHUNK) {
        __syncthreads();
        for (int i = tid; i < 128 * (KCHUNK / 4); i += 256) {
            int r = i >> 4;
            int q = i & 15;
            float4 v = make_float4(0.f, 0.f, 0.f, 0.f);
            int gr = row0 + r;
            if (gr < nrows) v = ((const float4*)X)[(size_t)gr * 32 + (kc >> 2) + q];
            *(float4*)(xs + r * XP + q * 4) = v;
        }
        __syncthreads();

#pragma unroll 8
        for (int k = 0; k < KCHUNK; k++) {
            const ulonglong2 wv0 = *(const ulonglong2*)(ws + (size_t)(kc + k) * NOUT + tx * 8);
            const ulonglong2 wv1 = *(const ulonglong2*)(ws + (size_t)(kc + k) * NOUT + tx * 8 + 4);
#pragma unroll
            for (int i = 0; i < TM; i++) {
                const ull xx = pack2(xs[(ty + i * TYN) * XP + k]);
                ffma2(acc[i][0], xx, wv0.x);
                ffma2(acc[i][1], xx, wv0.y);
                ffma2(acc[i][2], xx, wv1.x);
                ffma2(acc[i][3], xx, wv1.y);
            }
        }
    }

#pragma unroll
    for (int i = 0; i < TM; i++) {
        const int r = row0 + ty + i * TYN;
        if (r < nrows) {
            const float dv = g_dinv[r];
            const float2 p0 = unpack2(acc[i][0]);
            const float2 p1 = unpack2(acc[i][1]);
            const float2 p2 = unpack2(acc[i][2]);
            const float2 p3 = unpack2(acc[i][3]);
            float4 o0, o1;
            o0.x = p0.x * dv; o0.y = p0.y * dv;
            o0.z = p1.x * dv; o0.w = p1.y * dv;
            o1.x = p2.x * dv; o1.y = p2.y * dv;
            o1.z = p3.x * dv; o1.w = p3.y * dv;
            const size_t base = (size_t)r * NOUT + tx * 8;
            *(float4*)(out + base)     = o0;
            *(float4*)(out + base + 4) = o1;
        }
    }
}

// ---------------------------------------------------------------------------
// Gather-aggregation, one warp per node.
//   acc = h[node] + sum_{e in in(node)} h[csr[e]]
//   layer 1 (F=128): out = relu(dinv*acc + b), float4/lane
//   layer 2 (F=64):  out = dinv*acc + b,       float2/lane
// ---------------------------------------------------------------------------
__global__ __launch_bounds__(256)
void agg128_relu_kernel(const float4* __restrict__ h,   // [N][32] float4
                        const float*  __restrict__ b,
                        float4* __restrict__ out, int N)
{
    const int warp = (blockIdx.x * blockDim.x + threadIdx.x) >> 5;
    const int lane = threadIdx.x & 31;
    if (warp >= N) return;
    const int n = warp;

    float4 acc = h[(size_t)n * 32 + lane];  // self-loop
    const int start = g_rowstart[n];
    const int end   = g_rowstart[n + 1];

    for (int base = start; base < end; base += 32) {
        const int nv  = min(32, end - base);
        const int idx = (base + lane < end) ? g_csr[base + lane] : 0;
        for (int t = 0; t < nv; t++) {
            const int s = __shfl_sync(0xffffffffu, idx, t);
            const float4 v = h[(size_t)s * 32 + lane];
            acc.x += v.x; acc.y += v.y; acc.z += v.z; acc.w += v.w;
        }
    }
    const float dv = g_dinv[n];
    const float4 bb = ((const float4*)b)[lane];
    float4 o;
    o.x = fmaxf(acc.x * dv + bb.x, 0.f);
    o.y = fmaxf(acc.y * dv + bb.y, 0.f);
    o.z = fmaxf(acc.z * dv + bb.z, 0.f);
    o.w = fmaxf(acc.w * dv + bb.w, 0.f);
    out[(size_t)n * 32 + lane] = o;
}

__global__ __launch_bounds__(256)
void agg64_kernel(const float2* __restrict__ h,   // [N][32] float2
                  const float*  __restrict__ b,
                  float2* __restrict__ out, int N)
{
    const int warp = (blockIdx.x * blockDim.x + threadIdx.x) >> 5;
    const int lane = threadIdx.x & 31;
    if (warp >= N) return;
    const int n = warp;

    float2 acc = h[(size_t)n * 32 + lane];  // self-loop
    const int start = g_rowstart[n];
    const int end   = g_rowstart[n + 1];

    for (int base = start; base < end; base += 32) {
        const int nv  = min(32, end - base);
        const int idx = (base + lane < end) ? g_csr[base + lane] : 0;
        for (int t = 0; t < nv; t++) {
            const int s = __shfl_sync(0xffffffffu, idx, t);
            const float2 v = h[(size_t)s * 32 + lane];
            acc.x += v.x; acc.y += v.y;
        }
    }
    const float dv = g_dinv[n];
    const float2 bb = ((const float2*)b)[lane];
    float2 o;
    o.x = acc.x * dv + bb.x;
    o.y = acc.y * dv + bb.y;
    out[(size_t)n * 32 + lane] = o;
}

// ---------------------------------------------------------------------------
// Launch
// ---------------------------------------------------------------------------
extern "C" void kernel_launch(void* const* d_in, const int* in_sizes, int n_in,
                              void* d_out, int out_size)
{
    const float* x  = (const float*)d_in[0];
    const int*   ei = (const int*)  d_in[1];
    const float* W1 = (const float*)d_in[2];
    const float* b1 = (const float*)d_in[3];
    const float* W2 = (const float*)d_in[4];
    const float* b2 = (const float*)d_in[5];
    float* out = (float*)d_out;

    const int N = in_sizes[0] / F_IN;
    const int E = in_sizes[1] / 2;
    const int* src = ei;
    const int* dst = ei + E;

    float *p_h1, *p_y1, *p_h2;
    cudaGetSymbolAddress((void**)&p_h1, g_h1);
    cudaGetSymbolAddress((void**)&p_y1, g_y1);
    cudaGetSymbolAddress((void**)&p_h2, g_h2);

    const int smem1 = (128 * F_HID + 128 * XP) * (int)sizeof(float);
    const int smem2 = (128 * F_OUT + 128 * XP) * (int)sizeof(float);
    cudaFuncSetAttribute(gemm_scale_kernel<F_HID>,
                         cudaFuncAttributeMaxDynamicSharedMemorySize, smem1);
    cudaFuncSetAttribute(gemm_scale_kernel<F_OUT>,
                         cudaFuncAttributeMaxDynamicSharedMemorySize, smem2);

    const int T = 256;

    // CSR build + dinv
    zero_cnt_kernel<<<(N + T - 1) / T, T>>>(N);
    hist_kernel<<<(E + T - 1) / T, T>>>(dst, E);
    scan_kernel<<<1, SCAN_T>>>(N);
    place_kernel<<<(E + T - 1) / T, T>>>(src, dst, E);

    // Layer 1
    const int gblk = (N + 127) / 128;
    gemm_scale_kernel<F_HID><<<gblk, T, smem1>>>(x, W1, p_h1, N);
    {
        const int warps_per_blk = T / 32;
        const int blocks = (N + warps_per_blk - 1) / warps_per_blk;
        agg128_relu_kernel<<<blocks, T>>>((const float4*)p_h1, b1, (float4*)p_y1, N);
    }

    // Layer 2
    gemm_scale_kernel<F_OUT><<<gblk, T, smem2>>>(p_y1, W2, p_h2, N);
    {
        const int warps_per_blk = T / 32;
        const int blocks = (N + warps_per_blk - 1) / warps_per_blk;
        agg64_kernel<<<blocks, T>>>((const float2*)p_h2, b2, (float2*)out, N);
    }
}

// round 5
// speedup vs baseline: 1.9131x; 1.6581x over previous
#include <cuda_runtime.h>
#include <cstdint>
#include <cstddef>

#define N_NODES 100000
#define N_EDGES 1600000
#define F_IN    128
#define F_HID   128
#define F_OUT   64

typedef unsigned long long ull;

#define SCB 1024                           // scan chunk size
#define NSCB ((N_NODES + SCB - 1) / SCB)   // 98 scan blocks

// ---------------------------------------------------------------------------
// Scratch (device globals)
// ---------------------------------------------------------------------------
__device__ int   g_cnt     [N_NODES];
__device__ int   g_rowstart[N_NODES + 1];
__device__ int   g_cursor  [N_NODES];
__device__ int   g_csr     [N_EDGES];
__device__ int   g_bsum    [NSCB];
__device__ int   g_boff    [NSCB];
__device__ int   g_total;
__device__ float g_dinv    [N_NODES];
__device__ float g_h1 [(size_t)N_NODES * F_HID];
__device__ float g_y1 [(size_t)N_NODES * F_HID];
__device__ float g_h2 [(size_t)N_NODES * F_OUT];

// ---------------------------------------------------------------------------
// Packed fp32x2 helpers (sm_100+)
// ---------------------------------------------------------------------------
__device__ __forceinline__ void ffma2(ull& d, ull a, ull b) {
    asm("fma.rn.f32x2 %0, %1, %2, %0;" : "+l"(d) : "l"(a), "l"(b));
}
__device__ __forceinline__ ull pack2(float x) {
    ull r; asm("mov.b64 %0, {%1, %1};" : "=l"(r) : "f"(x)); return r;
}
__device__ __forceinline__ float2 unpack2(ull v) {
    float2 r; asm("mov.b64 {%0, %1}, %2;" : "=f"(r.x), "=f"(r.y) : "l"(v)); return r;
}

// ---------------------------------------------------------------------------
// CSR build: histogram -> 3-phase scan -> cursor placement
// ---------------------------------------------------------------------------
__global__ void zero_cnt_kernel(int n) {
    int i = blockIdx.x * blockDim.x + threadIdx.x;
    if (i < n) g_cnt[i] = 0;
}

__global__ void hist_kernel(const int* __restrict__ dst, int E) {
    int e = blockIdx.x * blockDim.x + threadIdx.x;
    if (e < E) atomicAdd(&g_cnt[dst[e]], 1);
}

__global__ void scan_local_kernel(int N) {
    __shared__ int s[SCB];
    const int t = threadIdx.x;
    const int i = blockIdx.x * SCB + t;
    const int v = (i < N) ? g_cnt[i] : 0;
    s[t] = v;
    __syncthreads();
    for (int off = 1; off < SCB; off <<= 1) {
        int u = (t >= off) ? s[t - off] : 0;
        __syncthreads();
        s[t] += u;
        __syncthreads();
    }
    const int incl = s[t];
    if (i < N) g_rowstart[i] = incl - v;            // exclusive, local
    if (t == SCB - 1) g_bsum[blockIdx.x] = incl;    // block total
}

__global__ void scan_block_kernel(int nb) {
    __shared__ int s[SCB];
    const int t = threadIdx.x;
    const int v = (t < nb) ? g_bsum[t] : 0;
    s[t] = v;
    __syncthreads();
    for (int off = 1; off < SCB; off <<= 1) {
        int u = (t >= off) ? s[t - off] : 0;
        __syncthreads();
        s[t] += u;
        __syncthreads();
    }
    if (t < nb) g_boff[t] = s[t] - v;               // exclusive
    if (t == nb - 1) g_total = s[t];
}

__global__ void scan_fix_kernel(int N) {
    const int i = blockIdx.x * blockDim.x + threadIdx.x;
    if (i < N) {
        const int rs = g_rowstart[i] + g_boff[i >> 10];   // SCB = 1024
        g_rowstart[i] = rs;
        g_cursor[i]   = rs;
        g_dinv[i]     = rsqrtf((float)g_cnt[i] + 1.0f);   // +1 self-loop
    }
    if (i == 0) g_rowstart[N] = g_total;
}

__global__ void place_kernel(const int* __restrict__ src,
                             const int* __restrict__ dst, int E) {
    int e = blockIdx.x * blockDim.x + threadIdx.x;
    if (e < E) {
        int d = dst[e];
        int p = atomicAdd(&g_cursor[d], 1);
        g_csr[p] = src[e];
    }
}

// ---------------------------------------------------------------------------
// Fused GEMM + dinv row-scale epilogue, packed fp32x2 math.
// xs staged TRANSPOSED (k-major, [KCHUNK][128]) so mainloop x reads are
// vector LDS.128 broadcast instead of 8 scalar LDS.32.
// ---------------------------------------------------------------------------
#define KCHUNK 64

template <int NOUT>
__global__ __launch_bounds__(256, 2)
void gemm_scale_kernel(const float* __restrict__ X,
                       const float* __restrict__ W,
                       float* __restrict__ out,
                       int nrows)
{
    constexpr int TXN = NOUT / 8;      // 16 (NOUT=128) or 8 (NOUT=64)
    constexpr int TYN = 256 / TXN;     // 16 or 32
    constexpr int TM  = 128 / TYN;     // 8 or 4 rows per thread (consecutive)

    extern __shared__ float sm[];
    float* ws = sm;                    // [128][NOUT]
    float* xs = sm + 128 * NOUT;       // [KCHUNK][128] k-major

    const int row0 = blockIdx.x * 128;
    const int tid  = threadIdx.x;
    const int tx   = tid % TXN;
    const int ty   = tid / TXN;

    {
        const float4* Wv = (const float4*)W;
        float4* wsv = (float4*)ws;
        for (int i = tid; i < 128 * NOUT / 4; i += 256) wsv[i] = Wv[i];
    }

    ull acc[TM][4];
#pragma unroll
    for (int i = 0; i < TM; i++)
#pragma unroll
        for (int j = 0; j < 4; j++) acc[i][j] = 0ull;

    for (int kc = 0; kc < 128; kc += KCHUNK) {
        __syncthreads();
        // Stage transposed: thread handles (q, r): q = k-group of 4, r = row.
        // Lanes span consecutive r -> STS conflict-free; gmem read is strided
        // (one 16B chunk per row) but L1/L2-absorbed.
        for (int i = tid; i < (KCHUNK / 4) * 128; i += 256) {
            const int q = i >> 7;       // 0..15
            const int r = i & 127;
            float4 v = make_float4(0.f, 0.f, 0.f, 0.f);
            const int gr = row0 + r;
            if (gr < nrows) v = ((const float4*)X)[(size_t)gr * 32 + (kc >> 2) + q];
            xs[(q * 4 + 0) * 128 + r] = v.x;
            xs[(q * 4 + 1) * 128 + r] = v.y;
            xs[(q * 4 + 2) * 128 + r] = v.z;
            xs[(q * 4 + 3) * 128 + r] = v.w;
        }
        __syncthreads();

#pragma unroll 8
        for (int k = 0; k < KCHUNK; k++) {
            const ulonglong2 wv0 = *(const ulonglong2*)(ws + (size_t)(kc + k) * NOUT + tx * 8);
            const ulonglong2 wv1 = *(const ulonglong2*)(ws + (size_t)(kc + k) * NOUT + tx * 8 + 4);
            const float* xr = xs + k * 128 + ty * TM;
            const float4 xa = *(const float4*)xr;
            if constexpr (TM == 8) {
                const float4 xb = *(const float4*)(xr + 4);
                const float xv[8] = {xa.x, xa.y, xa.z, xa.w, xb.x, xb.y, xb.z, xb.w};
#pragma unroll
                for (int i = 0; i < 8; i++) {
                    const ull xx = pack2(xv[i]);
                    ffma2(acc[i][0], xx, wv0.x);
                    ffma2(acc[i][1], xx, wv0.y);
                    ffma2(acc[i][2], xx, wv1.x);
                    ffma2(acc[i][3], xx, wv1.y);
                }
            } else {
                const float xv[4] = {xa.x, xa.y, xa.z, xa.w};
#pragma unroll
                for (int i = 0; i < 4; i++) {
                    const ull xx = pack2(xv[i]);
                    ffma2(acc[i][0], xx, wv0.x);
                    ffma2(acc[i][1], xx, wv0.y);
                    ffma2(acc[i][2], xx, wv1.x);
                    ffma2(acc[i][3], xx, wv1.y);
                }
            }
        }
    }

#pragma unroll
    for (int i = 0; i < TM; i++) {
        const int r = row0 + ty * TM + i;
        if (r < nrows) {
            const float dv = g_dinv[r];
            const float2 p0 = unpack2(acc[i][0]);
            const float2 p1 = unpack2(acc[i][1]);
            const float2 p2 = unpack2(acc[i][2]);
            const float2 p3 = unpack2(acc[i][3]);
            float4 o0, o1;
            o0.x = p0.x * dv; o0.y = p0.y * dv;
            o0.z = p1.x * dv; o0.w = p1.y * dv;
            o1.x = p2.x * dv; o1.y = p2.y * dv;
            o1.z = p3.x * dv; o1.w = p3.y * dv;
            const size_t base = (size_t)r * NOUT + tx * 8;
            *(float4*)(out + base)     = o0;
            *(float4*)(out + base + 4) = o1;
        }
    }
}

// ---------------------------------------------------------------------------
// Gather-aggregation, no shfl, manual unroll-4 for MLP.
// Index loads are warp-uniform (broadcast). Rows gathered as float4/lane.
// ---------------------------------------------------------------------------
__global__ __launch_bounds__(256)
void agg128_relu_kernel(const float4* __restrict__ h,   // [N][32]
                        const float*  __restrict__ b,
                        float4* __restrict__ out, int N)
{
    const int n    = (blockIdx.x * blockDim.x + threadIdx.x) >> 5;
    const int lane = threadIdx.x & 31;
    if (n >= N) return;

    float4 acc = h[(size_t)n * 32 + lane];  // self-loop
    const int start = g_rowstart[n];
    const int end   = g_rowstart[n + 1];

    int e = start;
    for (; e + 4 <= end; e += 4) {
        const int s0 = __ldg(g_csr + e);
        const int s1 = __ldg(g_csr + e + 1);
        const int s2 = __ldg(g_csr + e + 2);
        const int s3 = __ldg(g_csr + e + 3);
        const float4 v0 = h[(size_t)s0 * 32 + lane];
        const float4 v1 = h[(size_t)s1 * 32 + lane];
        const float4 v2 = h[(size_t)s2 * 32 + lane];
        const float4 v3 = h[(size_t)s3 * 32 + lane];
        acc.x += v0.x + v1.x + v2.x + v3.x;
        acc.y += v0.y + v1.y + v2.y + v3.y;
        acc.z += v0.z + v1.z + v2.z + v3.z;
        acc.w += v0.w + v1.w + v2.w + v3.w;
    }
    for (; e < end; e++) {
        const int s = __ldg(g_csr + e);
        const float4 v = h[(size_t)s * 32 + lane];
        acc.x += v.x; acc.y += v.y; acc.z += v.z; acc.w += v.w;
    }

    const float dv = g_dinv[n];
    const float4 bb = ((const float4*)b)[lane];
    float4 o;
    o.x = fmaxf(acc.x * dv + bb.x, 0.f);
    o.y = fmaxf(acc.y * dv + bb.y, 0.f);
    o.z = fmaxf(acc.z * dv + bb.z, 0.f);
    o.w = fmaxf(acc.w * dv + bb.w, 0.f);
    out[(size_t)n * 32 + lane] = o;
}

// F=64: 2 nodes per warp, 16 lanes (float4 each) per node.
__global__ __launch_bounds__(256)
void agg64_kernel(const float4* __restrict__ h,   // [N][16]
                  const float*  __restrict__ b,
                  float4* __restrict__ out, int N)
{
    const int pair = (blockIdx.x * blockDim.x + threadIdx.x) >> 5;
    const int half = (threadIdx.x >> 4) & 1;
    const int lane = threadIdx.x & 15;
    const int n = pair * 2 + half;
    if (n >= N) return;

    float4 acc = h[(size_t)n * 16 + lane];  // self-loop
    const int start = g_rowstart[n];
    const int end   = g_rowstart[n + 1];

    int e = start;
    for (; e + 4 <= end; e += 4) {
        const int s0 = __ldg(g_csr + e);
        const int s1 = __ldg(g_csr + e + 1);
        const int s2 = __ldg(g_csr + e + 2);
        const int s3 = __ldg(g_csr + e + 3);
        const float4 v0 = h[(size_t)s0 * 16 + lane];
        const float4 v1 = h[(size_t)s1 * 16 + lane];
        const float4 v2 = h[(size_t)s2 * 16 + lane];
        const float4 v3 = h[(size_t)s3 * 16 + lane];
        acc.x += v0.x + v1.x + v2.x + v3.x;
        acc.y += v0.y + v1.y + v2.y + v3.y;
        acc.z += v0.z + v1.z + v2.z + v3.z;
        acc.w += v0.w + v1.w + v2.w + v3.w;
    }
    for (; e < end; e++) {
        const int s = __ldg(g_csr + e);
        const float4 v = h[(size_t)s * 16 + lane];
        acc.x += v.x; acc.y += v.y; acc.z += v.z; acc.w += v.w;
    }

    const float dv = g_dinv[n];
    const float4 bb = ((const float4*)b)[lane];
    float4 o;
    o.x = acc.x * dv + bb.x;
    o.y = acc.y * dv + bb.y;
    o.z = acc.z * dv + bb.z;
    o.w = acc.w * dv + bb.w;
    out[(size_t)n * 16 + lane] = o;
}

// ---------------------------------------------------------------------------
// Launch
// ---------------------------------------------------------------------------
extern "C" void kernel_launch(void* const* d_in, const int* in_sizes, int n_in,
                              void* d_out, int out_size)
{
    const float* x  = (const float*)d_in[0];
    const int*   ei = (const int*)  d_in[1];
    const float* W1 = (const float*)d_in[2];
    const float* b1 = (const float*)d_in[3];
    const float* W2 = (const float*)d_in[4];
    const float* b2 = (const float*)d_in[5];
    float* out = (float*)d_out;

    const int N = in_sizes[0] / F_IN;
    const int E = in_sizes[1] / 2;
    const int* src = ei;
    const int* dst = ei + E;

    float *p_h1, *p_y1, *p_h2;
    cudaGetSymbolAddress((void**)&p_h1, g_h1);
    cudaGetSymbolAddress((void**)&p_y1, g_y1);
    cudaGetSymbolAddress((void**)&p_h2, g_h2);

    const int smem1 = (128 * F_HID + KCHUNK * 128) * (int)sizeof(float);  // 96 KB
    const int smem2 = (128 * F_OUT + KCHUNK * 128) * (int)sizeof(float);  // 64 KB
    cudaFuncSetAttribute(gemm_scale_kernel<F_HID>,
                         cudaFuncAttributeMaxDynamicSharedMemorySize, smem1);
    cudaFuncSetAttribute(gemm_scale_kernel<F_OUT>,
                         cudaFuncAttributeMaxDynamicSharedMemorySize, smem2);

    const int T = 256;
    const int nscb = (N + SCB - 1) / SCB;

    // CSR build + dinv
    zero_cnt_kernel<<<(N + T - 1) / T, T>>>(N);
    hist_kernel<<<(E + T - 1) / T, T>>>(dst, E);
    scan_local_kernel<<<nscb, SCB>>>(N);
    scan_block_kernel<<<1, SCB>>>(nscb);
    scan_fix_kernel<<<(N + T - 1) / T, T>>>(N);
    place_kernel<<<(E + T - 1) / T, T>>>(src, dst, E);

    // Layer 1
    const int gblk = (N + 127) / 128;
    gemm_scale_kernel<F_HID><<<gblk, T, smem1>>>(x, W1, p_h1, N);
    {
        const int warps = N;                      // 1 warp per node
        const int blocks = (warps * 32 + T - 1) / T;
        agg128_relu_kernel<<<blocks, T>>>((const float4*)p_h1, b1, (float4*)p_y1, N);
    }

    // Layer 2
    gemm_scale_kernel<F_OUT><<<gblk, T, smem2>>>(p_y1, W2, p_h2, N);
    {
        const int pairs = (N + 1) / 2;            // 2 nodes per warp
        const int blocks = (pairs * 32 + T - 1) / T;
        agg64_kernel<<<blocks, T>>>((const float4*)p_h2, b2, (float4*)out, N);
    }
}

// round 6
// speedup vs baseline: 1.9629x; 1.0261x over previous
#include <cuda_runtime.h>
#include <cstdint>
#include <cstddef>

#define N_NODES 100000
#define N_EDGES 1600000
#define F_IN    128
#define F_HID   128
#define F_OUT   64

typedef unsigned long long ull;

#define SCB 1024
#define NSCB ((N_NODES + SCB - 1) / SCB)

// ---------------------------------------------------------------------------
// Scratch (device globals)
// ---------------------------------------------------------------------------
__device__ int   g_cnt     [N_NODES];
__device__ int   g_rowstart[N_NODES + 1];
__device__ int   g_cursor  [N_NODES];
__device__ int   g_csr     [N_EDGES];
__device__ int   g_bsum    [NSCB];
__device__ int   g_boff    [NSCB];
__device__ int   g_total;
__device__ float g_dinv    [N_NODES];
__device__ float g_h1 [(size_t)N_NODES * F_HID];   // x @ W1 (UNSCALED)
__device__ float g_y1 [(size_t)N_NODES * F_HID];   // relu(dinv*agg + b1)
__device__ float g_h2 [(size_t)N_NODES * F_OUT];   // dinv * (y1 @ W2)

// ---------------------------------------------------------------------------
// Packed fp32x2 helpers (sm_100+)
// ---------------------------------------------------------------------------
__device__ __forceinline__ void ffma2(ull& d, ull a, ull b) {
    asm("fma.rn.f32x2 %0, %1, %2, %0;" : "+l"(d) : "l"(a), "l"(b));
}
__device__ __forceinline__ ull pack2(float x) {
    ull r; asm("mov.b64 %0, {%1, %1};" : "=l"(r) : "f"(x)); return r;
}
__device__ __forceinline__ float2 unpack2(ull v) {
    float2 r; asm("mov.b64 {%0, %1}, %2;" : "=f"(r.x), "=f"(r.y) : "l"(v)); return r;
}

// ---------------------------------------------------------------------------
// CSR build: histogram -> 3-phase scan -> cursor placement
// ---------------------------------------------------------------------------
__global__ void zero_cnt_kernel(int n) {
    int i = blockIdx.x * blockDim.x + threadIdx.x;
    if (i < n) g_cnt[i] = 0;
}

__global__ void hist_kernel(const int* __restrict__ dst, int E) {
    int e = blockIdx.x * blockDim.x + threadIdx.x;
    if (e < E) atomicAdd(&g_cnt[dst[e]], 1);
}

__global__ void scan_local_kernel(int N) {
    __shared__ int s[SCB];
    const int t = threadIdx.x;
    const int i = blockIdx.x * SCB + t;
    const int v = (i < N) ? g_cnt[i] : 0;
    s[t] = v;
    __syncthreads();
    for (int off = 1; off < SCB; off <<= 1) {
        int u = (t >= off) ? s[t - off] : 0;
        __syncthreads();
        s[t] += u;
        __syncthreads();
    }
    const int incl = s[t];
    if (i < N) g_rowstart[i] = incl - v;
    if (t == SCB - 1) g_bsum[blockIdx.x] = incl;
}

__global__ void scan_block_kernel(int nb) {
    __shared__ int s[SCB];
    const int t = threadIdx.x;
    const int v = (t < nb) ? g_bsum[t] : 0;
    s[t] = v;
    __syncthreads();
    for (int off = 1; off < SCB; off <<= 1) {
        int u = (t >= off) ? s[t - off] : 0;
        __syncthreads();
        s[t] += u;
        __syncthreads();
    }
    if (t < nb) g_boff[t] = s[t] - v;
    if (t == nb - 1) g_total = s[t];
}

__global__ void scan_fix_kernel(int N) {
    const int i = blockIdx.x * blockDim.x + threadIdx.x;
    if (i < N) {
        const int rs = g_rowstart[i] + g_boff[i >> 10];
        g_rowstart[i] = rs;
        g_cursor[i]   = rs;
        g_dinv[i]     = rsqrtf((float)g_cnt[i] + 1.0f);
    }
    if (i == 0) g_rowstart[N] = g_total;
}

__global__ void place_kernel(const int* __restrict__ src,
                             const int* __restrict__ dst, int E) {
    int e = blockIdx.x * blockDim.x + threadIdx.x;
    if (e < E) {
        int d = dst[e];
        int p = atomicAdd(&g_cursor[d], 1);
        g_csr[p] = src[e];
    }
}

// ---------------------------------------------------------------------------
// GEMM, packed fp32x2, transposed-x staging. SCALE: multiply rows by dinv.
// ---------------------------------------------------------------------------
#define KCHUNK 64

template <int NOUT, bool SCALE>
__global__ __launch_bounds__(256, 2)
void gemm_kernel(const float* __restrict__ X,
                 const float* __restrict__ W,
                 float* __restrict__ out,
                 int nrows)
{
    constexpr int TXN = NOUT / 8;
    constexpr int TYN = 256 / TXN;
    constexpr int TM  = 128 / TYN;

    extern __shared__ float sm[];
    float* ws = sm;                    // [128][NOUT]
    float* xs = sm + 128 * NOUT;       // [KCHUNK][128] k-major

    const int row0 = blockIdx.x * 128;
    const int tid  = threadIdx.x;
    const int tx   = tid % TXN;
    const int ty   = tid / TXN;

    {
        const float4* Wv = (const float4*)W;
        float4* wsv = (float4*)ws;
        for (int i = tid; i < 128 * NOUT / 4; i += 256) wsv[i] = Wv[i];
    }

    ull acc[TM][4];
#pragma unroll
    for (int i = 0; i < TM; i++)
#pragma unroll
        for (int j = 0; j < 4; j++) acc[i][j] = 0ull;

    for (int kc = 0; kc < 128; kc += KCHUNK) {
        __syncthreads();
        for (int i = tid; i < (KCHUNK / 4) * 128; i += 256) {
            const int q = i >> 7;
            const int r = i & 127;
            float4 v = make_float4(0.f, 0.f, 0.f, 0.f);
            const int gr = row0 + r;
            if (gr < nrows) v = ((const float4*)X)[(size_t)gr * 32 + (kc >> 2) + q];
            xs[(q * 4 + 0) * 128 + r] = v.x;
            xs[(q * 4 + 1) * 128 + r] = v.y;
            xs[(q * 4 + 2) * 128 + r] = v.z;
            xs[(q * 4 + 3) * 128 + r] = v.w;
        }
        __syncthreads();

#pragma unroll 8
        for (int k = 0; k < KCHUNK; k++) {
            const ulonglong2 wv0 = *(const ulonglong2*)(ws + (size_t)(kc + k) * NOUT + tx * 8);
            const ulonglong2 wv1 = *(const ulonglong2*)(ws + (size_t)(kc + k) * NOUT + tx * 8 + 4);
            const float* xr = xs + k * 128 + ty * TM;
            const float4 xa = *(const float4*)xr;
            if constexpr (TM == 8) {
                const float4 xb = *(const float4*)(xr + 4);
                const float xv[8] = {xa.x, xa.y, xa.z, xa.w, xb.x, xb.y, xb.z, xb.w};
#pragma unroll
                for (int i = 0; i < 8; i++) {
                    const ull xx = pack2(xv[i]);
                    ffma2(acc[i][0], xx, wv0.x);
                    ffma2(acc[i][1], xx, wv0.y);
                    ffma2(acc[i][2], xx, wv1.x);
                    ffma2(acc[i][3], xx, wv1.y);
                }
            } else {
                const float xv[4] = {xa.x, xa.y, xa.z, xa.w};
#pragma unroll
                for (int i = 0; i < 4; i++) {
                    const ull xx = pack2(xv[i]);
                    ffma2(acc[i][0], xx, wv0.x);
                    ffma2(acc[i][1], xx, wv0.y);
                    ffma2(acc[i][2], xx, wv1.x);
                    ffma2(acc[i][3], xx, wv1.y);
                }
            }
        }
    }

#pragma unroll
    for (int i = 0; i < TM; i++) {
        const int r = row0 + ty * TM + i;
        if (r < nrows) {
            float dv = 1.0f;
            if constexpr (SCALE) dv = g_dinv[r];
            const float2 p0 = unpack2(acc[i][0]);
            const float2 p1 = unpack2(acc[i][1]);
            const float2 p2 = unpack2(acc[i][2]);
            const float2 p3 = unpack2(acc[i][3]);
            float4 o0, o1;
            o0.x = p0.x * dv; o0.y = p0.y * dv;
            o0.z = p1.x * dv; o0.w = p1.y * dv;
            o1.x = p2.x * dv; o1.y = p2.y * dv;
            o1.z = p3.x * dv; o1.w = p3.y * dv;
            const size_t base = (size_t)r * NOUT + tx * 8;
            *(float4*)(out + base)     = o0;
            *(float4*)(out + base + 4) = o1;
        }
    }
}

// ---------------------------------------------------------------------------
// Layer-1 aggregation: h is UNSCALED; apply dinv[s] per edge, dinv[n] twice.
//   out = relu(dinv[n]*(dinv[n]*h[n] + sum dinv[s]*h[s]) + b)
// ---------------------------------------------------------------------------
__global__ __launch_bounds__(256)
void agg128_relu_kernel(const float4* __restrict__ h,   // [N][32]
                        const float*  __restrict__ b,
                        float4* __restrict__ out, int N)
{
    const int n    = (blockIdx.x * blockDim.x + threadIdx.x) >> 5;
    const int lane = threadIdx.x & 31;
    if (n >= N) return;

    const float dvn = g_dinv[n];
    const float4 hs = h[(size_t)n * 32 + lane];
    float4 acc;
    acc.x = hs.x * dvn; acc.y = hs.y * dvn;
    acc.z = hs.z * dvn; acc.w = hs.w * dvn;

    const int start = g_rowstart[n];
    const int end   = g_rowstart[n + 1];

    int e = start;
    for (; e + 4 <= end; e += 4) {
        const int s0 = __ldg(g_csr + e);
        const int s1 = __ldg(g_csr + e + 1);
        const int s2 = __ldg(g_csr + e + 2);
        const int s3 = __ldg(g_csr + e + 3);
        const float d0 = __ldg(g_dinv + s0);
        const float d1 = __ldg(g_dinv + s1);
        const float d2 = __ldg(g_dinv + s2);
        const float d3 = __ldg(g_dinv + s3);
        const float4 v0 = h[(size_t)s0 * 32 + lane];
        const float4 v1 = h[(size_t)s1 * 32 + lane];
        const float4 v2 = h[(size_t)s2 * 32 + lane];
        const float4 v3 = h[(size_t)s3 * 32 + lane];
        acc.x += v0.x * d0 + v1.x * d1 + v2.x * d2 + v3.x * d3;
        acc.y += v0.y * d0 + v1.y * d1 + v2.y * d2 + v3.y * d3;
        acc.z += v0.z * d0 + v1.z * d1 + v2.z * d2 + v3.z * d3;
        acc.w += v0.w * d0 + v1.w * d1 + v2.w * d2 + v3.w * d3;
    }
    for (; e < end; e++) {
        const int s = __ldg(g_csr + e);
        const float d = __ldg(g_dinv + s);
        const float4 v = h[(size_t)s * 32 + lane];
        acc.x += v.x * d; acc.y += v.y * d;
        acc.z += v.z * d; acc.w += v.w * d;
    }

    const float4 bb = ((const float4*)b)[lane];
    float4 o;
    o.x = fmaxf(acc.x * dvn + bb.x, 0.f);
    o.y = fmaxf(acc.y * dvn + bb.y, 0.f);
    o.z = fmaxf(acc.z * dvn + bb.z, 0.f);
    o.w = fmaxf(acc.w * dvn + bb.w, 0.f);
    out[(size_t)n * 32 + lane] = o;
}

// Layer-2 aggregation: h pre-scaled by dinv. 2 nodes/warp, 16 lanes each.
__global__ __launch_bounds__(256)
void agg64_kernel(const float4* __restrict__ h,   // [N][16]
                  const float*  __restrict__ b,
                  float4* __restrict__ out, int N)
{
    const int pair = (blockIdx.x * blockDim.x + threadIdx.x) >> 5;
    const int half = (threadIdx.x >> 4) & 1;
    const int lane = threadIdx.x & 15;
    const int n = pair * 2 + half;
    if (n >= N) return;

    float4 acc = h[(size_t)n * 16 + lane];  // self-loop
    const int start = g_rowstart[n];
    const int end   = g_rowstart[n + 1];

    int e = start;
    for (; e + 4 <= end; e += 4) {
        const int s0 = __ldg(g_csr + e);
        const int s1 = __ldg(g_csr + e + 1);
        const int s2 = __ldg(g_csr + e + 2);
        const int s3 = __ldg(g_csr + e + 3);
        const float4 v0 = h[(size_t)s0 * 16 + lane];
        const float4 v1 = h[(size_t)s1 * 16 + lane];
        const float4 v2 = h[(size_t)s2 * 16 + lane];
        const float4 v3 = h[(size_t)s3 * 16 + lane];
        acc.x += v0.x + v1.x + v2.x + v3.x;
        acc.y += v0.y + v1.y + v2.y + v3.y;
        acc.z += v0.z + v1.z + v2.z + v3.z;
        acc.w += v0.w + v1.w + v2.w + v3.w;
    }
    for (; e < end; e++) {
        const int s = __ldg(g_csr + e);
        const float4 v = h[(size_t)s * 16 + lane];
        acc.x += v.x; acc.y += v.y; acc.z += v.z; acc.w += v.w;
    }

    const float dv = g_dinv[n];
    const float4 bb = ((const float4*)b)[lane];
    float4 o;
    o.x = acc.x * dv + bb.x;
    o.y = acc.y * dv + bb.y;
    o.z = acc.z * dv + bb.z;
    o.w = acc.w * dv + bb.w;
    out[(size_t)n * 16 + lane] = o;
}

// ---------------------------------------------------------------------------
// Launch: CSR build on aux stream, GEMM1 on main stream, event fork/join.
// ---------------------------------------------------------------------------
extern "C" void kernel_launch(void* const* d_in, const int* in_sizes, int n_in,
                              void* d_out, int out_size)
{
    const float* x  = (const float*)d_in[0];
    const int*   ei = (const int*)  d_in[1];
    const float* W1 = (const float*)d_in[2];
    const float* b1 = (const float*)d_in[3];
    const float* W2 = (const float*)d_in[4];
    const float* b2 = (const float*)d_in[5];
    float* out = (float*)d_out;

    const int N = in_sizes[0] / F_IN;
    const int E = in_sizes[1] / 2;
    const int* src = ei;
    const int* dst = ei + E;

    float *p_h1, *p_y1, *p_h2;
    cudaGetSymbolAddress((void**)&p_h1, g_h1);
    cudaGetSymbolAddress((void**)&p_y1, g_y1);
    cudaGetSymbolAddress((void**)&p_h2, g_h2);

    const int smem1 = (128 * F_HID + KCHUNK * 128) * (int)sizeof(float);
    const int smem2 = (128 * F_OUT + KCHUNK * 128) * (int)sizeof(float);
    cudaFuncSetAttribute(gemm_kernel<F_HID, false>,
                         cudaFuncAttributeMaxDynamicSharedMemorySize, smem1);
    cudaFuncSetAttribute(gemm_kernel<F_OUT, true>,
                         cudaFuncAttributeMaxDynamicSharedMemorySize, smem2);

    // One-time resources (created on the uncaptured correctness call)
    static cudaStream_t s_aux = nullptr;
    static cudaEvent_t  ev_fork = nullptr, ev_join = nullptr;
    if (s_aux == nullptr) {
        cudaStreamCreateWithFlags(&s_aux, cudaStreamNonBlocking);
        cudaEventCreateWithFlags(&ev_fork, cudaEventDisableTiming);
        cudaEventCreateWithFlags(&ev_join, cudaEventDisableTiming);
    }

    const int T = 256;
    const int nscb = (N + SCB - 1) / SCB;
    const int gblk = (N + 127) / 128;

    // Fork: CSR build on s_aux, GEMM1 on main stream, concurrently.
    cudaEventRecord(ev_fork, 0);
    cudaStreamWaitEvent(s_aux, ev_fork, 0);

    zero_cnt_kernel  <<<(N + T - 1) / T, T, 0, s_aux>>>(N);
    hist_kernel      <<<(E + T - 1) / T, T, 0, s_aux>>>(dst, E);
    scan_local_kernel<<<nscb, SCB, 0, s_aux>>>(N);
    scan_block_kernel<<<1, SCB, 0, s_aux>>>(nscb);
    scan_fix_kernel  <<<(N + T - 1) / T, T, 0, s_aux>>>(N);
    place_kernel     <<<(E + T - 1) / T, T, 0, s_aux>>>(src, dst, E);
    cudaEventRecord(ev_join, s_aux);

    gemm_kernel<F_HID, false><<<gblk, T, smem1>>>(x, W1, p_h1, N);  // main stream

    // Join
    cudaStreamWaitEvent(0, ev_join, 0);

    // agg1 -> GEMM2 -> agg2 (serial chain, main stream)
    {
        const int blocks = (N * 32 + T - 1) / T;
        agg128_relu_kernel<<<blocks, T>>>((const float4*)p_h1, b1, (float4*)p_y1, N);
    }
    gemm_kernel<F_OUT, true><<<gblk, T, smem2>>>(p_y1, W2, p_h2, N);
    {
        const int pairs = (N + 1) / 2;
        const int blocks = (pairs * 32 + T - 1) / T;
        agg64_kernel<<<blocks, T>>>((const float4*)p_h2, b2, (float4*)out, N);
    }
}

// round 7
// speedup vs baseline: 2.0140x; 1.0260x over previous
#include <cuda_runtime.h>
#include <cstdint>
#include <cstddef>

#define N_NODES 100000
#define N_EDGES 1600000
#define F_IN    128
#define F_HID   128
#define F_OUT   64

typedef unsigned long long ull;

#define SCB 1024
#define NSCB ((N_NODES + SCB - 1) / SCB)

// ---------------------------------------------------------------------------
// Scratch (device globals)
// ---------------------------------------------------------------------------
__device__ int   g_cnt     [N_NODES];
__device__ int   g_rowstart[N_NODES + 1];
__device__ int   g_cursor  [N_NODES];
__device__ int   g_csr     [N_EDGES];
__device__ int   g_bsum    [NSCB];
__device__ int   g_boff    [NSCB];
__device__ int   g_total;
__device__ float g_dinv    [N_NODES];
__device__ float g_h1 [(size_t)N_NODES * F_HID];   // x @ W1 (UNSCALED)
__device__ float g_y1 [(size_t)N_NODES * F_HID];   // relu(dinv*agg + b1)
__device__ float g_h2 [(size_t)N_NODES * F_OUT];   // dinv * (y1 @ W2)

// ---------------------------------------------------------------------------
// Packed fp32x2 helpers (sm_100+)
// ---------------------------------------------------------------------------
__device__ __forceinline__ void ffma2(ull& d, ull a, ull b) {
    asm("fma.rn.f32x2 %0, %1, %2, %0;" : "+l"(d) : "l"(a), "l"(b));
}
__device__ __forceinline__ ull pack2(float x) {
    ull r; asm("mov.b64 %0, {%1, %1};" : "=l"(r) : "f"(x)); return r;
}
__device__ __forceinline__ float2 unpack2(ull v) {
    float2 r; asm("mov.b64 {%0, %1}, %2;" : "=f"(r.x), "=f"(r.y) : "l"(v)); return r;
}

// ---------------------------------------------------------------------------
// CSR build: histogram -> 3-phase scan -> cursor placement
// ---------------------------------------------------------------------------
__global__ void zero_cnt_kernel(int n) {
    int i = blockIdx.x * blockDim.x + threadIdx.x;
    if (i < n) g_cnt[i] = 0;
}

__global__ void hist_kernel(const int* __restrict__ dst, int E) {
    int e = blockIdx.x * blockDim.x + threadIdx.x;
    if (e < E) atomicAdd(&g_cnt[dst[e]], 1);
}

__global__ void scan_local_kernel(int N) {
    __shared__ int s[SCB];
    const int t = threadIdx.x;
    const int i = blockIdx.x * SCB + t;
    const int v = (i < N) ? g_cnt[i] : 0;
    s[t] = v;
    __syncthreads();
    for (int off = 1; off < SCB; off <<= 1) {
        int u = (t >= off) ? s[t - off] : 0;
        __syncthreads();
        s[t] += u;
        __syncthreads();
    }
    const int incl = s[t];
    if (i < N) g_rowstart[i] = incl - v;
    if (t == SCB - 1) g_bsum[blockIdx.x] = incl;
}

__global__ void scan_block_kernel(int nb) {
    __shared__ int s[SCB];
    const int t = threadIdx.x;
    const int v = (t < nb) ? g_bsum[t] : 0;
    s[t] = v;
    __syncthreads();
    for (int off = 1; off < SCB; off <<= 1) {
        int u = (t >= off) ? s[t - off] : 0;
        __syncthreads();
        s[t] += u;
        __syncthreads();
    }
    if (t < nb) g_boff[t] = s[t] - v;
    if (t == nb - 1) g_total = s[t];
}

__global__ void scan_fix_kernel(int N) {
    const int i = blockIdx.x * blockDim.x + threadIdx.x;
    if (i < N) {
        const int rs = g_rowstart[i] + g_boff[i >> 10];
        g_rowstart[i] = rs;
        g_cursor[i]   = rs;
        g_dinv[i]     = rsqrtf((float)g_cnt[i] + 1.0f);
    }
    if (i == 0) g_rowstart[N] = g_total;
}

__global__ void place_kernel(const int* __restrict__ src,
                             const int* __restrict__ dst, int E) {
    int e = blockIdx.x * blockDim.x + threadIdx.x;
    if (e < E) {
        int d = dst[e];
        int p = atomicAdd(&g_cursor[d], 1);
        g_csr[p] = src[e];
    }
}

// ---------------------------------------------------------------------------
// GEMM, packed fp32x2, transposed-x staging. SCALE: multiply rows by dinv.
// ---------------------------------------------------------------------------
#define KCHUNK 64

template <int NOUT, bool SCALE>
__global__ __launch_bounds__(256, 2)
void gemm_kernel(const float* __restrict__ X,
                 const float* __restrict__ W,
                 float* __restrict__ out,
                 int nrows)
{
    constexpr int TXN = NOUT / 8;
    constexpr int TYN = 256 / TXN;
    constexpr int TM  = 128 / TYN;

    extern __shared__ float sm[];
    float* ws = sm;                    // [128][NOUT]
    float* xs = sm + 128 * NOUT;       // [KCHUNK][128] k-major

    const int row0 = blockIdx.x * 128;
    const int tid  = threadIdx.x;
    const int tx   = tid % TXN;
    const int ty   = tid / TXN;

    {
        const float4* Wv = (const float4*)W;
        float4* wsv = (float4*)ws;
        for (int i = tid; i < 128 * NOUT / 4; i += 256) wsv[i] = Wv[i];
    }

    ull acc[TM][4];
#pragma unroll
    for (int i = 0; i < TM; i++)
#pragma unroll
        for (int j = 0; j < 4; j++) acc[i][j] = 0ull;

    for (int kc = 0; kc < 128; kc += KCHUNK) {
        __syncthreads();
        for (int i = tid; i < (KCHUNK / 4) * 128; i += 256) {
            const int q = i >> 7;
            const int r = i & 127;
            float4 v = make_float4(0.f, 0.f, 0.f, 0.f);
            const int gr = row0 + r;
            if (gr < nrows) v = ((const float4*)X)[(size_t)gr * 32 + (kc >> 2) + q];
            xs[(q * 4 + 0) * 128 + r] = v.x;
            xs[(q * 4 + 1) * 128 + r] = v.y;
            xs[(q * 4 + 2) * 128 + r] = v.z;
            xs[(q * 4 + 3) * 128 + r] = v.w;
        }
        __syncthreads();

#pragma unroll 8
        for (int k = 0; k < KCHUNK; k++) {
            const ulonglong2 wv0 = *(const ulonglong2*)(ws + (size_t)(kc + k) * NOUT + tx * 8);
            const ulonglong2 wv1 = *(const ulonglong2*)(ws + (size_t)(kc + k) * NOUT + tx * 8 + 4);
            const float* xr = xs + k * 128 + ty * TM;
            const float4 xa = *(const float4*)xr;
            if constexpr (TM == 8) {
                const float4 xb = *(const float4*)(xr + 4);
                const float xv[8] = {xa.x, xa.y, xa.z, xa.w, xb.x, xb.y, xb.z, xb.w};
#pragma unroll
                for (int i = 0; i < 8; i++) {
                    const ull xx = pack2(xv[i]);
                    ffma2(acc[i][0], xx, wv0.x);
                    ffma2(acc[i][1], xx, wv0.y);
                    ffma2(acc[i][2], xx, wv1.x);
                    ffma2(acc[i][3], xx, wv1.y);
                }
            } else {
                const float xv[4] = {xa.x, xa.y, xa.z, xa.w};
#pragma unroll
                for (int i = 0; i < 4; i++) {
                    const ull xx = pack2(xv[i]);
                    ffma2(acc[i][0], xx, wv0.x);
                    ffma2(acc[i][1], xx, wv0.y);
                    ffma2(acc[i][2], xx, wv1.x);
                    ffma2(acc[i][3], xx, wv1.y);
                }
            }
        }
    }

#pragma unroll
    for (int i = 0; i < TM; i++) {
        const int r = row0 + ty * TM + i;
        if (r < nrows) {
            float dv = 1.0f;
            if constexpr (SCALE) dv = g_dinv[r];
            const float2 p0 = unpack2(acc[i][0]);
            const float2 p1 = unpack2(acc[i][1]);
            const float2 p2 = unpack2(acc[i][2]);
            const float2 p3 = unpack2(acc[i][3]);
            float4 o0, o1;
            o0.x = p0.x * dv; o0.y = p0.y * dv;
            o0.z = p1.x * dv; o0.w = p1.y * dv;
            o1.x = p2.x * dv; o1.y = p2.y * dv;
            o1.z = p3.x * dv; o1.w = p3.y * dv;
            const size_t base = (size_t)r * NOUT + tx * 8;
            *(float4*)(out + base)     = o0;
            *(float4*)(out + base + 4) = o1;
        }
    }
}

// ---------------------------------------------------------------------------
// Layer-1 aggregation: h is UNSCALED; apply dinv[s] per edge, dinv[n] twice.
//   out = relu(dinv[n]*(dinv[n]*h[n] + sum dinv[s]*h[s]) + b)
// ---------------------------------------------------------------------------
__global__ __launch_bounds__(256)
void agg128_relu_kernel(const float4* __restrict__ h,   // [N][32]
                        const float*  __restrict__ b,
                        float4* __restrict__ out, int N)
{
    const int n    = (blockIdx.x * blockDim.x + threadIdx.x) >> 5;
    const int lane = threadIdx.x & 31;
    if (n >= N) return;

    const float dvn = g_dinv[n];
    const float4 hs = h[(size_t)n * 32 + lane];
    float4 acc;
    acc.x = hs.x * dvn; acc.y = hs.y * dvn;
    acc.z = hs.z * dvn; acc.w = hs.w * dvn;

    const int start = g_rowstart[n];
    const int end   = g_rowstart[n + 1];

    int e = start;
    for (; e + 4 <= end; e += 4) {
        const int s0 = __ldg(g_csr + e);
        const int s1 = __ldg(g_csr + e + 1);
        const int s2 = __ldg(g_csr + e + 2);
        const int s3 = __ldg(g_csr + e + 3);
        const float d0 = __ldg(g_dinv + s0);
        const float d1 = __ldg(g_dinv + s1);
        const float d2 = __ldg(g_dinv + s2);
        const float d3 = __ldg(g_dinv + s3);
        const float4 v0 = h[(size_t)s0 * 32 + lane];
        const float4 v1 = h[(size_t)s1 * 32 + lane];
        const float4 v2 = h[(size_t)s2 * 32 + lane];
        const float4 v3 = h[(size_t)s3 * 32 + lane];
        acc.x += v0.x * d0 + v1.x * d1 + v2.x * d2 + v3.x * d3;
        acc.y += v0.y * d0 + v1.y * d1 + v2.y * d2 + v3.y * d3;
        acc.z += v0.z * d0 + v1.z * d1 + v2.z * d2 + v3.z * d3;
        acc.w += v0.w * d0 + v1.w * d1 + v2.w * d2 + v3.w * d3;
    }
    for (; e < end; e++) {
        const int s = __ldg(g_csr + e);
        const float d = __ldg(g_dinv + s);
        const float4 v = h[(size_t)s * 32 + lane];
        acc.x += v.x * d; acc.y += v.y * d;
        acc.z += v.z * d; acc.w += v.w * d;
    }

    const float4 bb = ((const float4*)b)[lane];
    float4 o;
    o.x = fmaxf(acc.x * dvn + bb.x, 0.f);
    o.y = fmaxf(acc.y * dvn + bb.y, 0.f);
    o.z = fmaxf(acc.z * dvn + bb.z, 0.f);
    o.w = fmaxf(acc.w * dvn + bb.w, 0.f);
    out[(size_t)n * 32 + lane] = o;
}

// Layer-2 aggregation: h pre-scaled by dinv. 2 nodes/warp, 16 lanes each.
__global__ __launch_bounds__(256)
void agg64_kernel(const float4* __restrict__ h,   // [N][16]
                  const float*  __restrict__ b,
                  float4* __restrict__ out, int N)
{
    const int pair = (blockIdx.x * blockDim.x + threadIdx.x) >> 5;
    const int half = (threadIdx.x >> 4) & 1;
    const int lane = threadIdx.x & 15;
    const int n = pair * 2 + half;
    if (n >= N) return;

    float4 acc = h[(size_t)n * 16 + lane];  // self-loop
    const int start = g_rowstart[n];
    const int end   = g_rowstart[n + 1];

    int e = start;
    for (; e + 4 <= end; e += 4) {
        const int s0 = __ldg(g_csr + e);
        const int s1 = __ldg(g_csr + e + 1);
        const int s2 = __ldg(g_csr + e + 2);
        const int s3 = __ldg(g_csr + e + 3);
        const float4 v0 = h[(size_t)s0 * 16 + lane];
        const float4 v1 = h[(size_t)s1 * 16 + lane];
        const float4 v2 = h[(size_t)s2 * 16 + lane];
        const float4 v3 = h[(size_t)s3 * 16 + lane];
        acc.x += v0.x + v1.x + v2.x + v3.x;
        acc.y += v0.y + v1.y + v2.y + v3.y;
        acc.z += v0.z + v1.z + v2.z + v3.z;
        acc.w += v0.w + v1.w + v2.w + v3.w;
    }
    for (; e < end; e++) {
        const int s = __ldg(g_csr + e);
        const float4 v = h[(size_t)s * 16 + lane];
        acc.x += v.x; acc.y += v.y; acc.z += v.z; acc.w += v.w;
    }

    const float dv = g_dinv[n];
    const float4 bb = ((const float4*)b)[lane];
    float4 o;
    o.x = acc.x * dv + bb.x;
    o.y = acc.y * dv + bb.y;
    o.z = acc.z * dv + bb.z;
    o.w = acc.w * dv + bb.w;
    out[(size_t)n * 16 + lane] = o;
}

// ---------------------------------------------------------------------------
// Launch: CSR build on aux stream, GEMM1 on main stream, event fork/join.
// ---------------------------------------------------------------------------
extern "C" void kernel_launch(void* const* d_in, const int* in_sizes, int n_in,
                              void* d_out, int out_size)
{
    const float* x  = (const float*)d_in[0];
    const int*   ei = (const int*)  d_in[1];
    const float* W1 = (const float*)d_in[2];
    const float* b1 = (const float*)d_in[3];
    const float* W2 = (const float*)d_in[4];
    const float* b2 = (const float*)d_in[5];
    float* out = (float*)d_out;

    const int N = in_sizes[0] / F_IN;
    const int E = in_sizes[1] / 2;
    const int* src = ei;
    const int* dst = ei + E;

    float *p_h1, *p_y1, *p_h2;
    cudaGetSymbolAddress((void**)&p_h1, g_h1);
    cudaGetSymbolAddress((void**)&p_y1, g_y1);
    cudaGetSymbolAddress((void**)&p_h2, g_h2);

    const int smem1 = (128 * F_HID + KCHUNK * 128) * (int)sizeof(float);
    const int smem2 = (128 * F_OUT + KCHUNK * 128) * (int)sizeof(float);
    cudaFuncSetAttribute(gemm_kernel<F_HID, false>,
                         cudaFuncAttributeMaxDynamicSharedMemorySize, smem1);
    cudaFuncSetAttribute(gemm_kernel<F_OUT, true>,
                         cudaFuncAttributeMaxDynamicSharedMemorySize, smem2);

    // One-time resources (created on the uncaptured correctness call)
    static cudaStream_t s_aux = nullptr;
    static cudaEvent_t  ev_fork = nullptr, ev_join = nullptr;
    if (s_aux == nullptr) {
        cudaStreamCreateWithFlags(&s_aux, cudaStreamNonBlocking);
        cudaEventCreateWithFlags(&ev_fork, cudaEventDisableTiming);
        cudaEventCreateWithFlags(&ev_join, cudaEventDisableTiming);
    }

    const int T = 256;
    const int nscb = (N + SCB - 1) / SCB;
    const int gblk = (N + 127) / 128;

    // Fork: CSR build on s_aux, GEMM1 on main stream, concurrently.
    cudaEventRecord(ev_fork, 0);
    cudaStreamWaitEvent(s_aux, ev_fork, 0);

    zero_cnt_kernel  <<<(N + T - 1) / T, T, 0, s_aux>>>(N);
    hist_kernel      <<<(E + T - 1) / T, T, 0, s_aux>>>(dst, E);
    scan_local_kernel<<<nscb, SCB, 0, s_aux>>>(N);
    scan_block_kernel<<<1, SCB, 0, s_aux>>>(nscb);
    scan_fix_kernel  <<<(N + T - 1) / T, T, 0, s_aux>>>(N);
    place_kernel     <<<(E + T - 1) / T, T, 0, s_aux>>>(src, dst, E);
    cudaEventRecord(ev_join, s_aux);

    gemm_kernel<F_HID, false><<<gblk, T, smem1>>>(x, W1, p_h1, N);  // main stream

    // Join
    cudaStreamWaitEvent(0, ev_join, 0);

    // agg1 -> GEMM2 -> agg2 (serial chain, main stream)
    {
        const int blocks = (N * 32 + T - 1) / T;
        agg128_relu_kernel<<<blocks, T>>>((const float4*)p_h1, b1, (float4*)p_y1, N);
    }
    gemm_kernel<F_OUT, true><<<gblk, T, smem2>>>(p_y1, W2, p_h2, N);
    {
        const int pairs = (N + 1) / 2;
        const int blocks = (pairs * 32 + T - 1) / T;
        agg64_kernel<<<blocks, T>>>((const float4*)p_h2, b2, (float4*)out, N);
    }
}